// round 11
// baseline (speedup 1.0000x reference)
#include <cuda_runtime.h>

#define BATCH 2048
#define NPTS  4095
#define TPB   512
#define CH    2048          // elements per pass
#define LEPT  4             // TPB*LEPT = CH
#define NQ    4             // 2 passes x 2 batches
#define NWARP (TPB/32)      // 16
#define GRID  (BATCH/2)

__device__ float g_partial[BATCH];
__device__ int   g_count = 0;

// 3 rotating buffers x 3 components x 2048 floats = 72 KB
#define SMEM_BYTES (3 * 3 * CH * 4)

extern __shared__ __align__(16) float sstage[];

__device__ __forceinline__ void phaseA(const float* __restrict__ s3b,
                                       const float* __restrict__ s2b,
                                       const float* __restrict__ dfb,
                                       int half,
                                       float* __restrict__ bx,
                                       float* __restrict__ by,
                                       float* __restrict__ bz,
                                       int t)
{
    #pragma unroll
    for (int k = 0; k < LEPT; k++) {
        const int i = t + k * TPB;          // 0..2047, coalesced
        const int g = i + half * CH;
        float vx = 0.f, vy = 0.f, vz = 0.f;
        if (g < NPTS) {                      // only g==4095 (half==1) fails
            float r3  = s3b[g];
            float th3 = s3b[g + NPTS];
            float ph3 = s3b[g + 2 * NPTS];
            float r2  = s2b[g];
            float th2 = s2b[g + NPTS];
            float ph2 = s2b[g + 2 * NPTS];
            float dt  = dfb[g];
            float dp  = dfb[g + NPTS];

            float st, ct, sp, cp;
            __sincosf(th3 + dt, &st, &ct);
            __sincosf(ph3 + dp, &sp, &cp);
            float rst = r3 * st;
            vx = rst * cp; vy = rst * sp; vz = r3 * ct;
            __sincosf(th2, &st, &ct);
            __sincosf(ph2, &sp, &cp);
            rst = r2 * st;
            vx -= rst * cp; vy -= rst * sp; vz -= r2 * ct;
        }
        bx[i] = vx; by[i] = vy; bz[i] = vz;
    }
}

__global__ void __launch_bounds__(TPB, 3)
mpd_fused_kernel(const float* __restrict__ o3,
                 const float* __restrict__ s3,
                 const float* __restrict__ o2,
                 const float* __restrict__ s2,
                 const float* __restrict__ df,
                 float* __restrict__ out)
{
    __shared__ float wt[NQ][3][NWARP];
    __shared__ float red0[NWARP], red1[NWARP];
    __shared__ int   is_last;

    const int b0 = blockIdx.x * 2;          // this block's two batches: b0, b0+1
    const int t = threadIdx.x;
    const unsigned lane = t & 31u;
    const unsigned warp = t >> 5;

    const float* __restrict__ s3b0 = s3 + (size_t)b0 * (3 * NPTS);
    const float* __restrict__ s2b0 = s2 + (size_t)b0 * (3 * NPTS);
    const float* __restrict__ dfb0 = df + (size_t)b0 * (2 * NPTS);
    // batch1 pointers are fixed offsets from batch0's
    const float* __restrict__ s3b1 = s3b0 + 3 * NPTS;
    const float* __restrict__ s2b1 = s2b0 + 3 * NPTS;
    const float* __restrict__ dfb1 = dfb0 + 2 * NPTS;

    // prologue: q=0 (batch0, half0) -> buffer 0
    phaseA(s3b0, s2b0, dfb0, 0, sstage, sstage + CH, sstage + 2 * CH, t);
    __syncthreads();

    float offx, offy, offz;
    {
        offx = o3[b0 * 3 + 0] - o2[b0 * 3 + 0];
        offy = o3[b0 * 3 + 1] - o2[b0 * 3 + 1];
        offz = o3[b0 * 3 + 2] - o2[b0 * 3 + 2];
    }
    float acc0 = 0.f, acc1 = 0.f;
    if (t == 0) acc0 = fabsf(offx) + fabsf(offy) + fabsf(offz);  // batch0 j=0

    const int base = LEPT * t;               // float4 slot

    #pragma unroll
    for (int q = 0; q < NQ; q++) {
        // q -> (batch qb, half qh); all compile-time after unroll
        const int qb = q >> 1, qh = q & 1;

        float* cbx = sstage + ((q % 3) * 3 + 0) * CH;
        float* cby = sstage + ((q % 3) * 3 + 1) * CH;
        float* cbz = sstage + ((q % 3) * 3 + 2) * CH;

        // issue next pass's load burst FIRST (covers this pass's scan)
        if (q + 1 < NQ) {
            const int nb = (q + 1) >> 1, nh = (q + 1) & 1;
            float* nbx = sstage + (((q + 1) % 3) * 3 + 0) * CH;
            float* nby = sstage + (((q + 1) % 3) * 3 + 1) * CH;
            float* nbz = sstage + (((q + 1) % 3) * 3 + 2) * CH;
            phaseA(nb ? s3b1 : s3b0, nb ? s2b1 : s2b0, nb ? dfb1 : dfb0,
                   nh, nbx, nby, nbz, t);
        }

        // batch rollover: reset running offset at start of batch1
        if (q == 2) {
            offx = o3[(b0 + 1) * 3 + 0] - o2[(b0 + 1) * 3 + 0];
            offy = o3[(b0 + 1) * 3 + 1] - o2[(b0 + 1) * 3 + 1];
            offz = o3[(b0 + 1) * 3 + 2] - o2[(b0 + 1) * 3 + 2];
            if (t == 0) acc1 = fabsf(offx) + fabsf(offy) + fabsf(offz);
        }

        // ---- B_a: thread totals (LDS.128) + warp scan ----
        float4 X = *reinterpret_cast<const float4*>(cbx + base);
        float4 Y = *reinterpret_cast<const float4*>(cby + base);
        float4 Z = *reinterpret_cast<const float4*>(cbz + base);
        const float tx = (X.x + X.y) + (X.z + X.w);
        const float ty = (Y.x + Y.y) + (Y.z + Y.w);
        const float tz = (Z.x + Z.y) + (Z.z + Z.w);

        float ix = tx, iy = ty, iz = tz;
        #pragma unroll
        for (int o = 1; o < 32; o <<= 1) {
            float ax = __shfl_up_sync(0xFFFFFFFFu, ix, o);
            float ay = __shfl_up_sync(0xFFFFFFFFu, iy, o);
            float az = __shfl_up_sync(0xFFFFFFFFu, iz, o);
            if (lane >= (unsigned)o) { ix += ax; iy += ay; iz += az; }
        }
        if (lane == 31) {
            wt[q][0][warp] = ix; wt[q][1][warp] = iy; wt[q][2][warp] = iz;
        }
        __syncthreads();    // fences wt[q]; also the 3-buffer rotation fence

        // ---- B_b: redundant warp-total scan + abs sweep ----
        float px = (lane < NWARP) ? wt[q][0][lane] : 0.f;
        float py = (lane < NWARP) ? wt[q][1][lane] : 0.f;
        float pz = (lane < NWARP) ? wt[q][2][lane] : 0.f;
        #pragma unroll
        for (int o = 1; o < NWARP; o <<= 1) {
            float ax = __shfl_up_sync(0xFFFFFFFFu, px, o);
            float ay = __shfl_up_sync(0xFFFFFFFFu, py, o);
            float az = __shfl_up_sync(0xFFFFFFFFu, pz, o);
            if (lane >= (unsigned)o) { px += ax; py += ay; pz += az; }
        }
        const unsigned src = (warp == 0) ? 0u : (warp - 1u);
        float wpx = __shfl_sync(0xFFFFFFFFu, px, src);
        float wpy = __shfl_sync(0xFFFFFFFFu, py, src);
        float wpz = __shfl_sync(0xFFFFFFFFu, pz, src);

        float ox = offx + (ix - tx) + ((warp == 0) ? 0.f : wpx);
        float oy = offy + (iy - ty) + ((warp == 0) ? 0.f : wpy);
        float oz = offz + (iz - tz) + ((warp == 0) ? 0.f : wpz);

        float a = 0.f;
        const int gbase = qh * CH + base;
        float xs[LEPT] = {X.x, X.y, X.z, X.w};
        float ys[LEPT] = {Y.x, Y.y, Y.z, Y.w};
        float zs[LEPT] = {Z.x, Z.y, Z.z, Z.w};
        #pragma unroll
        for (int k = 0; k < LEPT; k++) {
            ox += xs[k]; oy += ys[k]; oz += zs[k];
            if (gbase + k < NPTS)
                a += fabsf(ox) + fabsf(oy) + fabsf(oz);
        }
        if (qb == 0) acc0 += a; else acc1 += a;

        // advance running offset by this pass's block total
        offx += __shfl_sync(0xFFFFFFFFu, px, NWARP - 1);
        offy += __shfl_sync(0xFFFFFFFFu, py, NWARP - 1);
        offz += __shfl_sync(0xFFFFFFFFu, pz, NWARP - 1);
    }

    // ---- block reduce of acc0 and acc1 (merged) ----
    #pragma unroll
    for (int o = 16; o > 0; o >>= 1) {
        acc0 += __shfl_down_sync(0xFFFFFFFFu, acc0, o);
        acc1 += __shfl_down_sync(0xFFFFFFFFu, acc1, o);
    }
    if (lane == 0) { red0[warp] = acc0; red1[warp] = acc1; }
    __syncthreads();
    if (warp == 0) {
        float a0 = (lane < NWARP) ? red0[lane] : 0.f;
        float a1 = (lane < NWARP) ? red1[lane] : 0.f;
        #pragma unroll
        for (int o = 16; o > 0; o >>= 1) {
            a0 += __shfl_down_sync(0xFFFFFFFFu, a0, o);
            a1 += __shfl_down_sync(0xFFFFFFFFu, a1, o);
        }
        if (lane == 0) {
            g_partial[b0]     = a0 * (1.0f / (NPTS + 1));
            g_partial[b0 + 1] = a1 * (1.0f / (NPTS + 1));
        }
    }

    // ---- fused deterministic final reduction in the last block ----
    if (t == 0) {
        __threadfence();
        int ticket = atomicAdd(&g_count, 1);
        is_last = (ticket == (int)gridDim.x - 1) ? 1 : 0;
    }
    __syncthreads();
    if (is_last) {
        float a = __ldcg(&g_partial[t])
                + __ldcg(&g_partial[t + TPB])
                + __ldcg(&g_partial[t + 2 * TPB])
                + __ldcg(&g_partial[t + 3 * TPB]);
        #pragma unroll
        for (int o = 16; o > 0; o >>= 1)
            a += __shfl_down_sync(0xFFFFFFFFu, a, o);
        if (lane == 0) red0[warp] = a;
        __syncthreads();
        if (warp == 0) {
            float v = (lane < NWARP) ? red0[lane] : 0.f;
            #pragma unroll
            for (int o = 16; o > 0; o >>= 1)
                v += __shfl_down_sync(0xFFFFFFFFu, v, o);
            if (lane == 0) {
                out[0] = v;
                atomicExch(&g_count, 0);   // reset for next graph replay
            }
        }
    }
}

extern "C" void kernel_launch(void* const* d_in, const int* in_sizes, int n_in,
                              void* d_out, int out_size)
{
    const float* o3 = (const float*)d_in[0];  // origin_3D        (B,3,1)
    const float* s3 = (const float*)d_in[1];  // spherical_3D     (B,3,N)
    const float* o2 = (const float*)d_in[2];  // origin_2D        (B,3,1)
    const float* s2 = (const float*)d_in[3];  // spherical_2D     (B,3,N)
    const float* df = (const float*)d_in[4];  // deformation_field(B,2,N)
    float* out = (float*)d_out;

    cudaFuncSetAttribute(mpd_fused_kernel,
                         cudaFuncAttributeMaxDynamicSharedMemorySize, SMEM_BYTES);
    mpd_fused_kernel<<<GRID, TPB, SMEM_BYTES>>>(o3, s3, o2, s2, df, out);
}